// round 13
// baseline (speedup 1.0000x reference)
#include <cuda_runtime.h>
#include <cuda_fp16.h>
#include <math.h>
#include <stdint.h>

#define Bb 8
#define Ss 256
#define Tt 32
#define Dd 512
#define NROWS 2048   // B*S
#define MROWS 256    // B*T

// Scratch (allocation-free rule: __device__ globals)
__device__ float g_H[NROWS * Dd];
__device__ float g_F[NROWS * Dd];
__device__ float g_A[MROWS * Dd];
__device__ float g_C[MROWS * Dd];

typedef unsigned long long ull;

// ---------------------------------------------------------------------------
// helpers
// ---------------------------------------------------------------------------
__device__ __forceinline__ uint32_t smem_to_u32(const void* p) {
    uint32_t a;
    asm("{ .reg .u64 t; cvta.to.shared.u64 t, %1; cvt.u32.u64 %0, t; }"
        : "=r"(a) : "l"(p));
    return a;
}
__device__ __forceinline__ void ldsm_x4(uint32_t* r, uint32_t addr) {
    asm volatile("ldmatrix.sync.aligned.m8n8.x4.shared.b16 {%0,%1,%2,%3}, [%4];"
        : "=r"(r[0]), "=r"(r[1]), "=r"(r[2]), "=r"(r[3]) : "r"(addr));
}
__device__ __forceinline__ void ldsm_x4_t(uint32_t* r, uint32_t addr) {
    asm volatile("ldmatrix.sync.aligned.m8n8.x4.trans.shared.b16 {%0,%1,%2,%3}, [%4];"
        : "=r"(r[0]), "=r"(r[1]), "=r"(r[2]), "=r"(r[3]) : "r"(addr));
}
__device__ __forceinline__ void mma_f16(float* d, const uint32_t* a, const uint32_t* b) {
    asm volatile("mma.sync.aligned.m16n8k16.row.col.f32.f16.f16.f32 "
        "{%0,%1,%2,%3}, {%4,%5,%6,%7}, {%8,%9}, {%0,%1,%2,%3};"
        : "+f"(d[0]), "+f"(d[1]), "+f"(d[2]), "+f"(d[3])
        : "r"(a[0]), "r"(a[1]), "r"(a[2]), "r"(a[3]), "r"(b[0]), "r"(b[1]));
}
__device__ __forceinline__ uint32_t pbh(__half a, __half b) {
    __half2 t; t.x = a; t.y = b;
    return *(uint32_t*)&t;
}
// packed f32x2 (FFMA2 path — proven on this target in R2/R3)
__device__ __forceinline__ ull pack2(float x, float y) {
    ull r;
    asm("mov.b64 %0, {%1, %2};" : "=l"(r) : "f"(x), "f"(y));
    return r;
}
__device__ __forceinline__ void unpack2(ull v, float& x, float& y) {
    asm("mov.b64 {%0, %1}, %2;" : "=f"(x), "=f"(y) : "l"(v));
}
__device__ __forceinline__ ull mul2(ull a, ull b) {
    ull d;
    asm("mul.rn.f32x2 %0, %1, %2;" : "=l"(d) : "l"(a), "l"(b));
    return d;
}
__device__ __forceinline__ ull fma2v(ull a, ull b, ull c) {
    ull d;
    asm("fma.rn.f32x2 %0, %1, %2, %3;" : "=l"(d) : "l"(a), "l"(b), "l"(c));
    return d;
}

// ---------------------------------------------------------------------------
// Mega-GEMM: out = tanh(src @ W + bias).
// fp16 asymmetric split: A = ahi + alo (exact to ~2^-21), B = one fp16 plane
// (2^-12 rel) -> 2 MMAs per 16-k group. Register-prefetch double-buffer.
// CTA: 64m x 128n, BK=32, 8 warps as 2m x 4n (warp 32x32) -> 288 CTAs
// (~2/SM so staging of one CTA overlaps MMA of the other).
// smem/buffer (halfs): Ahi[64*40] Alo[64*40] Bh[32*136] = 9472.
// Blocks: [0,128) H (K=512) | [128,144) A | [144,160) C | [160,288) F (K=128)
// ---------------------------------------------------------------------------
#define A_ELE (64 * 40)
#define B_ELE (32 * 136)
#define BUF_ELE (2 * A_ELE + B_ELE)          // 9472 halfs
#define GEMM_SMEM (2 * BUF_ELE * 2)          // 37888 bytes

__global__ void __launch_bounds__(256, 2)
megagemm_mma(const float* __restrict__ enc, const float* __restrict__ z,
             const float* __restrict__ outp,
             const float* __restrict__ W1, const float* __restrict__ b1,
             const float* __restrict__ W2, const float* __restrict__ b2,
             const float* __restrict__ W3, const float* __restrict__ b3,
             const float* __restrict__ W4, const float* __restrict__ b4,
             float* __restrict__ H, float* __restrict__ F,
             float* __restrict__ A, float* __restrict__ C)
{
    extern __shared__ __half sbuf[];

    int bid = blockIdx.x;
    const float *src, *W, *bias;
    float* dst;
    int K;
    if (bid < 128)      { src = enc;  W = W1; bias = b1; dst = H; K = 512; }
    else if (bid < 144) { src = outp; W = W2; bias = b2; dst = A; K = 512; bid -= 128; }
    else if (bid < 160) { src = outp; W = W4; bias = b4; dst = C; K = 512; bid -= 144; }
    else                { src = z;    W = W3; bias = b3; dst = F; K = 128; bid -= 160; }
    const int nb = bid & 3;          // 512/128 = 4 n-blocks
    const int mb = bid >> 2;
    const int m0 = mb * 64, n0 = nb * 128;

    const int tid  = threadIdx.x;
    const int lane = tid & 31;
    const int wid  = tid >> 5;
    const int wm   = wid & 1;     // 32 m rows
    const int wn   = wid >> 1;    // 32 n cols

    // staging coordinates
    const int am  = tid >> 3;             // A row base (0..31, + q*32)
    const int akq = (tid & 7) * 4;        // A k-quad
    const int bk  = tid >> 3;             // B k-row (0..31)
    const int bn  = (tid & 7) * 16;       // B n-base

    float acc[2][4][4];
    #pragma unroll
    for (int i = 0; i < 2; i++)
        #pragma unroll
        for (int j = 0; j < 4; j++)
            #pragma unroll
            for (int q = 0; q < 4; q++) acc[i][j][q] = 0.f;

    const int nch = K >> 5;
    float4 ra[2], rb[4];

    // Prologue: load chunk 0
    #pragma unroll
    for (int q = 0; q < 2; q++)
        ra[q] = *(const float4*)&src[(size_t)(m0 + am + q * 32) * K + akq];
    #pragma unroll
    for (int q = 0; q < 4; q++)
        rb[q] = *(const float4*)&W[(size_t)bk * 512 + n0 + bn + q * 4];

    for (int c = 0; c < nch; c++) {
        const int buf = c & 1;
        __half* Ahi = sbuf + buf * BUF_ELE;
        __half* Alo = Ahi + A_ELE;
        __half* Bh  = Alo + A_ELE;

        // Convert prefetched registers -> smem
        #pragma unroll
        for (int q = 0; q < 2; q++) {
            float xs[4] = {ra[q].x, ra[q].y, ra[q].z, ra[q].w};
            __half h[4], l[4];
            #pragma unroll
            for (int j = 0; j < 4; j++) {
                h[j] = __float2half_rn(xs[j]);
                l[j] = __float2half_rn(xs[j] - __half2float(h[j]));
            }
            uint2 uh; uh.x = pbh(h[0], h[1]); uh.y = pbh(h[2], h[3]);
            uint2 ul; ul.x = pbh(l[0], l[1]); ul.y = pbh(l[2], l[3]);
            *(uint2*)&Ahi[(am + q * 32) * 40 + akq] = uh;
            *(uint2*)&Alo[(am + q * 32) * 40 + akq] = ul;
        }
        #pragma unroll
        for (int q = 0; q < 4; q++) {
            float xs[4] = {rb[q].x, rb[q].y, rb[q].z, rb[q].w};
            uint2 uh;
            uh.x = pbh(__float2half_rn(xs[0]), __float2half_rn(xs[1]));
            uh.y = pbh(__float2half_rn(xs[2]), __float2half_rn(xs[3]));
            *(uint2*)&Bh[bk * 136 + bn + q * 4] = uh;
        }
        __syncthreads();

        // Prefetch next chunk while MMAs run
        if (c + 1 < nch) {
            const int k0g = (c + 1) * 32;
            #pragma unroll
            for (int q = 0; q < 2; q++)
                ra[q] = *(const float4*)&src[(size_t)(m0 + am + q * 32) * K + k0g + akq];
            #pragma unroll
            for (int q = 0; q < 4; q++)
                rb[q] = *(const float4*)&W[(size_t)(k0g + bk) * 512 + n0 + bn + q * 4];
        }

        const uint32_t aHiB = smem_to_u32(Ahi);
        const uint32_t aLoB = smem_to_u32(Alo);
        const uint32_t bHB  = smem_to_u32(Bh);

        #pragma unroll
        for (int ks = 0; ks < 2; ks++) {
            const int k0 = ks * 16;
            uint32_t ah[2][4], al[2][4];
            #pragma unroll
            for (int mi = 0; mi < 2; mi++) {
                int row = wm * 32 + mi * 16 + (lane & 15);
                uint32_t off = (uint32_t)(row * 40 + k0 + (lane >> 4) * 8) * 2;
                ldsm_x4(ah[mi], aHiB + off);
                ldsm_x4(al[mi], aLoB + off);
            }
            #pragma unroll
            for (int nc = 0; nc < 2; nc++) {
                int krow = k0 + (lane & 15);
                int ncol = wn * 32 + nc * 16 + (lane >> 4) * 8;
                uint32_t off = (uint32_t)(krow * 136 + ncol) * 2;
                uint32_t bh[4];
                ldsm_x4_t(bh, bHB + off);
                #pragma unroll
                for (int mi = 0; mi < 2; mi++) {
                    mma_f16(acc[mi][nc*2+0], ah[mi], bh);
                    mma_f16(acc[mi][nc*2+0], al[mi], bh);
                    mma_f16(acc[mi][nc*2+1], ah[mi], bh + 2);
                    mma_f16(acc[mi][nc*2+1], al[mi], bh + 2);
                }
            }
        }
        __syncthreads();
    }

    // Epilogue: bias + tanh + store
    #pragma unroll
    for (int mi = 0; mi < 2; mi++) {
        #pragma unroll
        for (int ni = 0; ni < 4; ni++) {
            int m_g = m0 + wm * 32 + mi * 16 + (lane >> 2);
            int n_g = n0 + wn * 32 + ni * 8 + (lane & 3) * 2;
            float2 bv = *(const float2*)&bias[n_g];
            float2 o0, o1;
            o0.x = tanhf(acc[mi][ni][0] + bv.x);
            o0.y = tanhf(acc[mi][ni][1] + bv.y);
            o1.x = tanhf(acc[mi][ni][2] + bv.x);
            o1.y = tanhf(acc[mi][ni][3] + bv.y);
            *(float2*)&dst[(size_t)m_g * 512 + n_g] = o0;
            *(float2*)&dst[(size_t)(m_g + 8) * 512 + n_g] = o1;
        }
    }
}

// ---------------------------------------------------------------------------
// Dual attention, f32x2-paired + 2-way s-split.
// Block = (b, d-tile 32), 1024 threads: tid = sq*512 + t*16 + dp
//   sq = s-half (0/1), t = 0..31, dp = d-pair (0..15).
// Warp = 2 t x 16 dp, same s -> every LDS.64 is a 128B broadcast (no
// conflicts); STG.64 = 2x128B segments. Thread-local softmax over its 128 s
// (tanh-bounded logits -> no max needed); halves merged via smem float2 red.
// Grid (16, 8) = 128 blocks, 104KB smem -> 1 block/SM, 32 warps/SM.
// ---------------------------------------------------------------------------
__global__ void __launch_bounds__(1024)
attn_kernel(const float* __restrict__ H, const float* __restrict__ F,
            const float* __restrict__ Amat, const float* __restrict__ Cmat,
            const float* __restrict__ enc, const float* __restrict__ outp,
            float* __restrict__ concat, float* __restrict__ attn)
{
    extern __shared__ float sm[];
    float* Hs = sm;            // [256][32]
    float* Fs = sm + 8192;     // [256][32]
    float* Es = sm + 16384;    // [256][32]
    __shared__ float2 red[1024];

    const int tid = threadIdx.x;
    const int dp2 = (tid & 15) * 2;   // d within 32-tile (pair base)
    const int t   = (tid >> 4) & 31;
    const int sq  = tid >> 9;
    const int d0  = blockIdx.x * 32;
    const int b   = blockIdx.y;

    for (int idx = tid; idx < 2048; idx += 1024) {
        int s  = idx >> 3;
        int dl = (idx & 7) << 2;
        size_t g = ((size_t)(b * Ss + s)) * Dd + d0 + dl;
        *(float4*)&Hs[s * 32 + dl] = *(const float4*)&H[g];
        *(float4*)&Fs[s * 32 + dl] = *(const float4*)&F[g];
        *(float4*)&Es[s * 32 + dl] = *(const float4*)&enc[g];
    }
    __syncthreads();

    const int m = b * Tt + t;
    const float L2E = 1.4426950408889634f;
    float2 av = *(const float2*)&Amat[(size_t)m * Dd + d0 + dp2];
    float2 cv = *(const float2*)&Cmat[(size_t)m * Dd + d0 + dp2];
    const ull a2 = pack2(av.x * L2E, av.y * L2E);
    const ull c2 = pack2(cv.x * L2E, cv.y * L2E);

    const int s0 = sq * 128;

    // Pass 1: partial softmax denominators over this s-half
    float sx = 0.f, sy = 0.f;
    #pragma unroll 4
    for (int s = s0; s < s0 + 128; s++) {
        float2 hf = *(const float2*)&Hs[s * 32 + dp2];
        float2 ff = *(const float2*)&Fs[s * 32 + dp2];
        ull l2 = fma2v(a2, pack2(hf.x, hf.y), mul2(c2, pack2(ff.x, ff.y)));
        float lx, ly; unpack2(l2, lx, ly);
        sx += exp2f(lx);
        sy += exp2f(ly);
    }
    red[tid] = make_float2(sx, sy);
    __syncthreads();
    {
        float2 o = red[tid ^ 512];
        sx += o.x; sy += o.y;
    }
    __syncthreads();   // protect red before pass-2 reuse
    const float ix = 1.f / sx, iy = 1.f / sy;
    const ull inv2 = pack2(ix, iy);

    // Pass 2: write gamma (STG.64) + partial context
    float cx = 0.f, cy = 0.f;
    float* ab = attn + (size_t)m * Ss * Dd + d0 + dp2;
    #pragma unroll 4
    for (int s = s0; s < s0 + 128; s++) {
        float2 hf = *(const float2*)&Hs[s * 32 + dp2];
        float2 ff = *(const float2*)&Fs[s * 32 + dp2];
        float2 ef = *(const float2*)&Es[s * 32 + dp2];
        ull l2 = fma2v(a2, pack2(hf.x, hf.y), mul2(c2, pack2(ff.x, ff.y)));
        float lx, ly; unpack2(l2, lx, ly);
        ull g2 = mul2(pack2(exp2f(lx), exp2f(ly)), inv2);
        float gx, gy; unpack2(g2, gx, gy);
        *(float2*)&ab[(size_t)s * Dd] = make_float2(gx, gy);
        cx = fmaf(gx, ef.x, cx);
        cy = fmaf(gy, ef.y, cy);
    }

    red[tid] = make_float2(cx, cy);
    __syncthreads();

    if (sq == 0) {
        float2 o = red[tid ^ 512];
        float2 ct; ct.x = cx + o.x; ct.y = cy + o.y;
        *(float2*)&concat[(size_t)m * (2 * Dd) + Dd + d0 + dp2] = ct;
    } else {
        *(float2*)&concat[(size_t)m * (2 * Dd) + d0 + dp2] =
            *(const float2*)&outp[(size_t)m * Dd + d0 + dp2];
    }
}

// ---------------------------------------------------------------------------
extern "C" void kernel_launch(void* const* d_in, const int* in_sizes, int n_in,
                              void* d_out, int out_size)
{
    const float* output = (const float*)d_in[0];   // [8,32,512]
    const float* enc    = (const float*)d_in[1];   // [256,8,512] flat [2048,512]
    const float* z      = (const float*)d_in[2];   // [8,256,128] flat [2048,128]
    const float* W1 = (const float*)d_in[3];
    const float* b1 = (const float*)d_in[4];
    const float* W2 = (const float*)d_in[5];
    const float* b2 = (const float*)d_in[6];
    const float* W3 = (const float*)d_in[7];
    const float* b3 = (const float*)d_in[8];
    const float* W4 = (const float*)d_in[9];
    const float* b4 = (const float*)d_in[10];

    float* concat = (float*)d_out;                       // [8,32,1024]
    float* attn   = concat + (size_t)Bb * Tt * 2 * Dd;   // [8,32,256,512]

    float *pH, *pF, *pA, *pC;
    cudaGetSymbolAddress((void**)&pH, g_H);
    cudaGetSymbolAddress((void**)&pF, g_F);
    cudaGetSymbolAddress((void**)&pA, g_A);
    cudaGetSymbolAddress((void**)&pC, g_C);

    cudaFuncSetAttribute(megagemm_mma, cudaFuncAttributeMaxDynamicSharedMemorySize, GEMM_SMEM);
    megagemm_mma<<<288, 256, GEMM_SMEM>>>(enc, z, output,
                                          W1, b1, W2, b2, W3, b3, W4, b4,
                                          pH, pF, pA, pC);

    const int smem_attn = 3 * 8192 * (int)sizeof(float);  // 98304
    cudaFuncSetAttribute(attn_kernel, cudaFuncAttributeMaxDynamicSharedMemorySize, smem_attn);
    attn_kernel<<<dim3(16, Bb), 1024, smem_attn>>>(pH, pF, pA, pC, enc, output, concat, attn);
}

// round 14
// speedup vs baseline: 1.0559x; 1.0559x over previous
#include <cuda_runtime.h>
#include <cuda_fp16.h>
#include <math.h>
#include <stdint.h>

#define Bb 8
#define Ss 256
#define Tt 32
#define Dd 512
#define NROWS 2048   // B*S
#define MROWS 256    // B*T

// Scratch (allocation-free rule: __device__ globals)
__device__ float g_H[NROWS * Dd];
__device__ float g_F[NROWS * Dd];
__device__ float g_A[MROWS * Dd];
__device__ float g_C[MROWS * Dd];

typedef unsigned long long ull;

// ---------------------------------------------------------------------------
// helpers
// ---------------------------------------------------------------------------
__device__ __forceinline__ uint32_t smem_to_u32(const void* p) {
    uint32_t a;
    asm("{ .reg .u64 t; cvta.to.shared.u64 t, %1; cvt.u32.u64 %0, t; }"
        : "=r"(a) : "l"(p));
    return a;
}
__device__ __forceinline__ void ldsm_x4(uint32_t* r, uint32_t addr) {
    asm volatile("ldmatrix.sync.aligned.m8n8.x4.shared.b16 {%0,%1,%2,%3}, [%4];"
        : "=r"(r[0]), "=r"(r[1]), "=r"(r[2]), "=r"(r[3]) : "r"(addr));
}
__device__ __forceinline__ void ldsm_x4_t(uint32_t* r, uint32_t addr) {
    asm volatile("ldmatrix.sync.aligned.m8n8.x4.trans.shared.b16 {%0,%1,%2,%3}, [%4];"
        : "=r"(r[0]), "=r"(r[1]), "=r"(r[2]), "=r"(r[3]) : "r"(addr));
}
__device__ __forceinline__ void mma_f16(float* d, const uint32_t* a, const uint32_t* b) {
    asm volatile("mma.sync.aligned.m16n8k16.row.col.f32.f16.f16.f32 "
        "{%0,%1,%2,%3}, {%4,%5,%6,%7}, {%8,%9}, {%0,%1,%2,%3};"
        : "+f"(d[0]), "+f"(d[1]), "+f"(d[2]), "+f"(d[3])
        : "r"(a[0]), "r"(a[1]), "r"(a[2]), "r"(a[3]), "r"(b[0]), "r"(b[1]));
}
__device__ __forceinline__ uint32_t pbh(__half a, __half b) {
    __half2 t; t.x = a; t.y = b;
    return *(uint32_t*)&t;
}
// packed f32x2
__device__ __forceinline__ ull pack2(float x, float y) {
    ull r;
    asm("mov.b64 %0, {%1, %2};" : "=l"(r) : "f"(x), "f"(y));
    return r;
}
__device__ __forceinline__ void unpack2(ull v, float& x, float& y) {
    asm("mov.b64 {%0, %1}, %2;" : "=f"(x), "=f"(y) : "l"(v));
}
__device__ __forceinline__ ull mul2(ull a, ull b) {
    ull d;
    asm("mul.rn.f32x2 %0, %1, %2;" : "=l"(d) : "l"(a), "l"(b));
    return d;
}
__device__ __forceinline__ ull fma2v(ull a, ull b, ull c) {
    ull d;
    asm("fma.rn.f32x2 %0, %1, %2, %3;" : "=l"(d) : "l"(a), "l"(b), "l"(c));
    return d;
}

// ---------------------------------------------------------------------------
// Mega-GEMM: out = tanh(src @ W + bias), pure fp16 operands (err ~2^-12 rel
// per operand, fp32 accumulate; tanh contracts + softmax renormalizes ->
// final rel_err ~2e-4, 5x under the 1e-3 gate). 1 MMA per 16-k group.
// Register-prefetch double-buffered pipeline (R12 proven scheme).
// CTA: 128m x 128n, BK=32, 8 warps as 4m x 2n (warp 32x64). 144 CTAs.
// smem/buffer (halfs): Ah[128*40]=5120, Bh[32*136]=4352 -> 9472.
// Blocks: [0,64) H (K=512) | [64,72) A | [72,80) C | [80,144) F (K=128 tail)
// ---------------------------------------------------------------------------
#define A_ELE (128 * 40)
#define B_ELE (32 * 136)
#define BUF_ELE (A_ELE + B_ELE)              // 9472 halfs
#define GEMM_SMEM (2 * BUF_ELE * 2)          // 37888 bytes

__global__ void __launch_bounds__(256)
megagemm_mma(const float* __restrict__ enc, const float* __restrict__ z,
             const float* __restrict__ outp,
             const float* __restrict__ W1, const float* __restrict__ b1,
             const float* __restrict__ W2, const float* __restrict__ b2,
             const float* __restrict__ W3, const float* __restrict__ b3,
             const float* __restrict__ W4, const float* __restrict__ b4,
             float* __restrict__ H, float* __restrict__ F,
             float* __restrict__ A, float* __restrict__ C)
{
    extern __shared__ __half sbuf[];

    int bid = blockIdx.x;
    const float *src, *W, *bias;
    float* dst;
    int K;
    if (bid < 64)      { src = enc;  W = W1; bias = b1; dst = H; K = 512; }
    else if (bid < 72) { src = outp; W = W2; bias = b2; dst = A; K = 512; bid -= 64; }
    else if (bid < 80) { src = outp; W = W4; bias = b4; dst = C; K = 512; bid -= 72; }
    else               { src = z;    W = W3; bias = b3; dst = F; K = 128; bid -= 80; }
    const int nb = bid & 3;          // 512/128 = 4 n-blocks
    const int mb = bid >> 2;
    const int m0 = mb * 128, n0 = nb * 128;

    const int tid  = threadIdx.x;
    const int lane = tid & 31;
    const int wid  = tid >> 5;
    const int wm   = wid & 3;     // 32 m rows
    const int wn   = wid >> 2;    // 64 n cols

    // staging coordinates
    const int am  = tid >> 3;             // A row base (+ q*32)
    const int akq = (tid & 7) * 4;        // A k-quad
    const int bk  = tid >> 3;             // B k-row (0..31)
    const int bn  = (tid & 7) * 16;       // B n-base (16 floats per thread)

    float acc[2][8][4];
    #pragma unroll
    for (int i = 0; i < 2; i++)
        #pragma unroll
        for (int j = 0; j < 8; j++)
            #pragma unroll
            for (int q = 0; q < 4; q++) acc[i][j][q] = 0.f;

    const int nch = K >> 5;
    float4 ra[4], rb[4];

    // Prologue: load chunk 0
    #pragma unroll
    for (int q = 0; q < 4; q++)
        ra[q] = *(const float4*)&src[(size_t)(m0 + am + q * 32) * K + akq];
    #pragma unroll
    for (int q = 0; q < 4; q++)
        rb[q] = *(const float4*)&W[(size_t)bk * 512 + n0 + bn + q * 4];

    for (int c = 0; c < nch; c++) {
        const int buf = c & 1;
        __half* Ah = sbuf + buf * BUF_ELE;
        __half* Bh = Ah + A_ELE;

        // Convert prefetched registers -> smem (single fp16 plane)
        #pragma unroll
        for (int q = 0; q < 4; q++) {
            float xs[4] = {ra[q].x, ra[q].y, ra[q].z, ra[q].w};
            uint2 uh;
            uh.x = pbh(__float2half_rn(xs[0]), __float2half_rn(xs[1]));
            uh.y = pbh(__float2half_rn(xs[2]), __float2half_rn(xs[3]));
            *(uint2*)&Ah[(am + q * 32) * 40 + akq] = uh;
        }
        #pragma unroll
        for (int q = 0; q < 4; q++) {
            float xs[4] = {rb[q].x, rb[q].y, rb[q].z, rb[q].w};
            uint2 uh;
            uh.x = pbh(__float2half_rn(xs[0]), __float2half_rn(xs[1]));
            uh.y = pbh(__float2half_rn(xs[2]), __float2half_rn(xs[3]));
            *(uint2*)&Bh[bk * 136 + bn + q * 4] = uh;
        }
        __syncthreads();

        // Prefetch next chunk while MMAs run
        if (c + 1 < nch) {
            const int k0g = (c + 1) * 32;
            #pragma unroll
            for (int q = 0; q < 4; q++)
                ra[q] = *(const float4*)&src[(size_t)(m0 + am + q * 32) * K + k0g + akq];
            #pragma unroll
            for (int q = 0; q < 4; q++)
                rb[q] = *(const float4*)&W[(size_t)(k0g + bk) * 512 + n0 + bn + q * 4];
        }

        const uint32_t aHB = smem_to_u32(Ah);
        const uint32_t bHB = smem_to_u32(Bh);

        #pragma unroll
        for (int ks = 0; ks < 2; ks++) {
            const int k0 = ks * 16;
            uint32_t ah[2][4];
            #pragma unroll
            for (int mi = 0; mi < 2; mi++) {
                int row = wm * 32 + mi * 16 + (lane & 15);
                uint32_t off = (uint32_t)(row * 40 + k0 + (lane >> 4) * 8) * 2;
                ldsm_x4(ah[mi], aHB + off);
            }
            #pragma unroll
            for (int nc = 0; nc < 4; nc++) {
                int krow = k0 + (lane & 15);
                int ncol = wn * 64 + nc * 16 + (lane >> 4) * 8;
                uint32_t off = (uint32_t)(krow * 136 + ncol) * 2;
                uint32_t bh[4];
                ldsm_x4_t(bh, bHB + off);
                #pragma unroll
                for (int mi = 0; mi < 2; mi++) {
                    mma_f16(acc[mi][nc*2+0], ah[mi], bh);
                    mma_f16(acc[mi][nc*2+1], ah[mi], bh + 2);
                }
            }
        }
        __syncthreads();
    }

    // Epilogue: bias + tanh + store
    #pragma unroll
    for (int mi = 0; mi < 2; mi++) {
        #pragma unroll
        for (int ni = 0; ni < 8; ni++) {
            int m_g = m0 + wm * 32 + mi * 16 + (lane >> 2);
            int n_g = n0 + wn * 64 + ni * 8 + (lane & 3) * 2;
            float2 bv = *(const float2*)&bias[n_g];
            float2 o0, o1;
            o0.x = tanhf(acc[mi][ni][0] + bv.x);
            o0.y = tanhf(acc[mi][ni][1] + bv.y);
            o1.x = tanhf(acc[mi][ni][2] + bv.x);
            o1.y = tanhf(acc[mi][ni][3] + bv.y);
            *(float2*)&dst[(size_t)m_g * 512 + n_g] = o0;
            *(float2*)&dst[(size_t)(m_g + 8) * 512 + n_g] = o1;
        }
    }
}

// ---------------------------------------------------------------------------
// Dual attention, f32x2-paired + 2-way s-split (R13 proven: 34.3us).
// Block = (b, d-tile 32), 1024 threads: tid = sq*512 + t*16 + dp
//   sq = s-half (0/1), t = 0..31, dp = d-pair (0..15).
// Warp = 2 t x 16 dp, same s -> every LDS.64 is a 128B broadcast; STG.64.
// Thread-local softmax over its 128 s (tanh-bounded logits -> no max);
// halves merged via smem float2 reduction.
// Grid (16, 8) = 128 blocks, 32 warps/SM.
// ---------------------------------------------------------------------------
__global__ void __launch_bounds__(1024)
attn_kernel(const float* __restrict__ H, const float* __restrict__ F,
            const float* __restrict__ Amat, const float* __restrict__ Cmat,
            const float* __restrict__ enc, const float* __restrict__ outp,
            float* __restrict__ concat, float* __restrict__ attn)
{
    extern __shared__ float sm[];
    float* Hs = sm;            // [256][32]
    float* Fs = sm + 8192;     // [256][32]
    float* Es = sm + 16384;    // [256][32]
    __shared__ float2 red[1024];

    const int tid = threadIdx.x;
    const int dp2 = (tid & 15) * 2;   // d within 32-tile (pair base)
    const int t   = (tid >> 4) & 31;
    const int sq  = tid >> 9;
    const int d0  = blockIdx.x * 32;
    const int b   = blockIdx.y;

    for (int idx = tid; idx < 2048; idx += 1024) {
        int s  = idx >> 3;
        int dl = (idx & 7) << 2;
        size_t g = ((size_t)(b * Ss + s)) * Dd + d0 + dl;
        *(float4*)&Hs[s * 32 + dl] = *(const float4*)&H[g];
        *(float4*)&Fs[s * 32 + dl] = *(const float4*)&F[g];
        *(float4*)&Es[s * 32 + dl] = *(const float4*)&enc[g];
    }
    __syncthreads();

    const int m = b * Tt + t;
    const float L2E = 1.4426950408889634f;
    float2 av = *(const float2*)&Amat[(size_t)m * Dd + d0 + dp2];
    float2 cv = *(const float2*)&Cmat[(size_t)m * Dd + d0 + dp2];
    const ull a2 = pack2(av.x * L2E, av.y * L2E);
    const ull c2 = pack2(cv.x * L2E, cv.y * L2E);

    const int s0 = sq * 128;

    // Pass 1: partial softmax denominators over this s-half
    float sx = 0.f, sy = 0.f;
    #pragma unroll 4
    for (int s = s0; s < s0 + 128; s++) {
        float2 hf = *(const float2*)&Hs[s * 32 + dp2];
        float2 ff = *(const float2*)&Fs[s * 32 + dp2];
        ull l2 = fma2v(a2, pack2(hf.x, hf.y), mul2(c2, pack2(ff.x, ff.y)));
        float lx, ly; unpack2(l2, lx, ly);
        sx += exp2f(lx);
        sy += exp2f(ly);
    }
    red[tid] = make_float2(sx, sy);
    __syncthreads();
    {
        float2 o = red[tid ^ 512];
        sx += o.x; sy += o.y;
    }
    __syncthreads();   // protect red before pass-2 reuse
    const float ix = 1.f / sx, iy = 1.f / sy;
    const ull inv2 = pack2(ix, iy);

    // Pass 2: write gamma (STG.64) + partial context
    float cx = 0.f, cy = 0.f;
    float* ab = attn + (size_t)m * Ss * Dd + d0 + dp2;
    #pragma unroll 4
    for (int s = s0; s < s0 + 128; s++) {
        float2 hf = *(const float2*)&Hs[s * 32 + dp2];
        float2 ff = *(const float2*)&Fs[s * 32 + dp2];
        float2 ef = *(const float2*)&Es[s * 32 + dp2];
        ull l2 = fma2v(a2, pack2(hf.x, hf.y), mul2(c2, pack2(ff.x, ff.y)));
        float lx, ly; unpack2(l2, lx, ly);
        ull g2 = mul2(pack2(exp2f(lx), exp2f(ly)), inv2);
        float gx, gy; unpack2(g2, gx, gy);
        *(float2*)&ab[(size_t)s * Dd] = make_float2(gx, gy);
        cx = fmaf(gx, ef.x, cx);
        cy = fmaf(gy, ef.y, cy);
    }

    red[tid] = make_float2(cx, cy);
    __syncthreads();

    if (sq == 0) {
        float2 o = red[tid ^ 512];
        float2 ct; ct.x = cx + o.x; ct.y = cy + o.y;
        *(float2*)&concat[(size_t)m * (2 * Dd) + Dd + d0 + dp2] = ct;
    } else {
        *(float2*)&concat[(size_t)m * (2 * Dd) + d0 + dp2] =
            *(const float2*)&outp[(size_t)m * Dd + d0 + dp2];
    }
}

// ---------------------------------------------------------------------------
extern "C" void kernel_launch(void* const* d_in, const int* in_sizes, int n_in,
                              void* d_out, int out_size)
{
    const float* output = (const float*)d_in[0];   // [8,32,512]
    const float* enc    = (const float*)d_in[1];   // [256,8,512] flat [2048,512]
    const float* z      = (const float*)d_in[2];   // [8,256,128] flat [2048,128]
    const float* W1 = (const float*)d_in[3];
    const float* b1 = (const float*)d_in[4];
    const float* W2 = (const float*)d_in[5];
    const float* b2 = (const float*)d_in[6];
    const float* W3 = (const float*)d_in[7];
    const float* b3 = (const float*)d_in[8];
    const float* W4 = (const float*)d_in[9];
    const float* b4 = (const float*)d_in[10];

    float* concat = (float*)d_out;                       // [8,32,1024]
    float* attn   = concat + (size_t)Bb * Tt * 2 * Dd;   // [8,32,256,512]

    float *pH, *pF, *pA, *pC;
    cudaGetSymbolAddress((void**)&pH, g_H);
    cudaGetSymbolAddress((void**)&pF, g_F);
    cudaGetSymbolAddress((void**)&pA, g_A);
    cudaGetSymbolAddress((void**)&pC, g_C);

    cudaFuncSetAttribute(megagemm_mma, cudaFuncAttributeMaxDynamicSharedMemorySize, GEMM_SMEM);
    megagemm_mma<<<144, 256, GEMM_SMEM>>>(enc, z, output,
                                          W1, b1, W2, b2, W3, b3, W4, b4,
                                          pH, pF, pA, pC);

    const int smem_attn = 3 * 8192 * (int)sizeof(float);  // 98304
    cudaFuncSetAttribute(attn_kernel, cudaFuncAttributeMaxDynamicSharedMemorySize, smem_attn);
    attn_kernel<<<dim3(16, Bb), 1024, smem_attn>>>(pH, pF, pA, pC, enc, output, concat, attn);
}

// round 15
// speedup vs baseline: 1.1191x; 1.0598x over previous
#include <cuda_runtime.h>
#include <cuda_fp16.h>
#include <math.h>
#include <stdint.h>

#define Bb 8
#define Ss 256
#define Tt 32
#define Dd 512
#define NROWS 2048   // B*S
#define MROWS 256    // B*T

// Scratch (allocation-free rule: __device__ globals)
__device__ float g_H[NROWS * Dd];
__device__ float g_F[NROWS * Dd];
__device__ float g_A[MROWS * Dd];
__device__ float g_C[MROWS * Dd];

typedef unsigned long long ull;

// ---------------------------------------------------------------------------
// helpers
// ---------------------------------------------------------------------------
__device__ __forceinline__ uint32_t smem_to_u32(const void* p) {
    uint32_t a;
    asm("{ .reg .u64 t; cvta.to.shared.u64 t, %1; cvt.u32.u64 %0, t; }"
        : "=r"(a) : "l"(p));
    return a;
}
__device__ __forceinline__ void ldsm_x4(uint32_t* r, uint32_t addr) {
    asm volatile("ldmatrix.sync.aligned.m8n8.x4.shared.b16 {%0,%1,%2,%3}, [%4];"
        : "=r"(r[0]), "=r"(r[1]), "=r"(r[2]), "=r"(r[3]) : "r"(addr));
}
__device__ __forceinline__ void ldsm_x4_t(uint32_t* r, uint32_t addr) {
    asm volatile("ldmatrix.sync.aligned.m8n8.x4.trans.shared.b16 {%0,%1,%2,%3}, [%4];"
        : "=r"(r[0]), "=r"(r[1]), "=r"(r[2]), "=r"(r[3]) : "r"(addr));
}
__device__ __forceinline__ void mma_f16(float* d, const uint32_t* a, const uint32_t* b) {
    asm volatile("mma.sync.aligned.m16n8k16.row.col.f32.f16.f16.f32 "
        "{%0,%1,%2,%3}, {%4,%5,%6,%7}, {%8,%9}, {%0,%1,%2,%3};"
        : "+f"(d[0]), "+f"(d[1]), "+f"(d[2]), "+f"(d[3])
        : "r"(a[0]), "r"(a[1]), "r"(a[2]), "r"(a[3]), "r"(b[0]), "r"(b[1]));
}
__device__ __forceinline__ uint32_t pbh(__half a, __half b) {
    __half2 t; t.x = a; t.y = b;
    return *(uint32_t*)&t;
}
// packed f32x2
__device__ __forceinline__ ull pack2(float x, float y) {
    ull r;
    asm("mov.b64 %0, {%1, %2};" : "=l"(r) : "f"(x), "f"(y));
    return r;
}
__device__ __forceinline__ void unpack2(ull v, float& x, float& y) {
    asm("mov.b64 {%0, %1}, %2;" : "=f"(x), "=f"(y) : "l"(v));
}
__device__ __forceinline__ ull mul2(ull a, ull b) {
    ull d;
    asm("mul.rn.f32x2 %0, %1, %2;" : "=l"(d) : "l"(a), "l"(b));
    return d;
}
__device__ __forceinline__ ull fma2v(ull a, ull b, ull c) {
    ull d;
    asm("fma.rn.f32x2 %0, %1, %2, %3;" : "=l"(d) : "l"(a), "l"(b), "l"(c));
    return d;
}

// ---------------------------------------------------------------------------
// Mega-GEMM: out = tanh(src @ W + bias), pure fp16 operands, fp32 accum.
// BK=64 (8 chunks for K=512) -> half the barrier/latency links of BK=32.
// Register-prefetch double-buffered pipeline.
// CTA: 128m x 128n, 8 warps as 4m x 2n (warp 32x64). 144 CTAs.
// smem/buffer (halfs): Ah[128*72]=9216, Bh[64*136]=8704 -> 17920.
// Blocks: [0,64) H (K=512) | [64,72) A | [72,80) C | [80,144) F (K=128 tail)
// ---------------------------------------------------------------------------
#define A_ELE (128 * 72)
#define B_ELE (64 * 136)
#define BUF_ELE (A_ELE + B_ELE)              // 17920 halfs
#define GEMM_SMEM (2 * BUF_ELE * 2)          // 71680 bytes

__global__ void __launch_bounds__(256)
megagemm_mma(const float* __restrict__ enc, const float* __restrict__ z,
             const float* __restrict__ outp,
             const float* __restrict__ W1, const float* __restrict__ b1,
             const float* __restrict__ W2, const float* __restrict__ b2,
             const float* __restrict__ W3, const float* __restrict__ b3,
             const float* __restrict__ W4, const float* __restrict__ b4,
             float* __restrict__ H, float* __restrict__ F,
             float* __restrict__ A, float* __restrict__ C)
{
    extern __shared__ __half sbuf[];

    int bid = blockIdx.x;
    const float *src, *W, *bias;
    float* dst;
    int K;
    if (bid < 64)      { src = enc;  W = W1; bias = b1; dst = H; K = 512; }
    else if (bid < 72) { src = outp; W = W2; bias = b2; dst = A; K = 512; bid -= 64; }
    else if (bid < 80) { src = outp; W = W4; bias = b4; dst = C; K = 512; bid -= 72; }
    else               { src = z;    W = W3; bias = b3; dst = F; K = 128; bid -= 80; }
    const int nb = bid & 3;          // 512/128 = 4 n-blocks
    const int mb = bid >> 2;
    const int m0 = mb * 128, n0 = nb * 128;

    const int tid  = threadIdx.x;
    const int lane = tid & 31;
    const int wid  = tid >> 5;
    const int wm   = wid & 3;     // 32 m rows
    const int wn   = wid >> 2;    // 64 n cols

    // staging coordinates: 4-thread groups cover one row's 64B runs
    const int ar = tid >> 2;             // A row base (0..63, +q*64)
    const int ac = (tid & 3) * 4;        // A col base (+j*16)
    const int br = tid >> 2;             // B row (0..63)
    const int bc = (tid & 3) * 4;        // B col base (+j*16)

    float acc[2][8][4];
    #pragma unroll
    for (int i = 0; i < 2; i++)
        #pragma unroll
        for (int j = 0; j < 8; j++)
            #pragma unroll
            for (int q = 0; q < 4; q++) acc[i][j][q] = 0.f;

    const int nch = K >> 6;
    float4 ra[8], rb[8];

    // Prologue: load chunk 0
    #pragma unroll
    for (int q = 0; q < 2; q++)
        #pragma unroll
        for (int j = 0; j < 4; j++)
            ra[q * 4 + j] = *(const float4*)&src[(size_t)(m0 + ar + q * 64) * K + ac + j * 16];
    #pragma unroll
    for (int j = 0; j < 8; j++)
        rb[j] = *(const float4*)&W[(size_t)br * 512 + n0 + bc + j * 16];

    for (int c = 0; c < nch; c++) {
        const int buf = c & 1;
        __half* Ah = sbuf + buf * BUF_ELE;
        __half* Bh = Ah + A_ELE;

        // Convert prefetched registers -> smem (single fp16 plane)
        #pragma unroll
        for (int q = 0; q < 2; q++)
            #pragma unroll
            for (int j = 0; j < 4; j++) {
                float4 v = ra[q * 4 + j];
                uint2 uh;
                uh.x = pbh(__float2half_rn(v.x), __float2half_rn(v.y));
                uh.y = pbh(__float2half_rn(v.z), __float2half_rn(v.w));
                *(uint2*)&Ah[(ar + q * 64) * 72 + ac + j * 16] = uh;
            }
        #pragma unroll
        for (int j = 0; j < 8; j++) {
            float4 v = rb[j];
            uint2 uh;
            uh.x = pbh(__float2half_rn(v.x), __float2half_rn(v.y));
            uh.y = pbh(__float2half_rn(v.z), __float2half_rn(v.w));
            *(uint2*)&Bh[br * 136 + bc + j * 16] = uh;
        }
        __syncthreads();

        // Prefetch next chunk while MMAs run
        if (c + 1 < nch) {
            const int k0g = (c + 1) * 64;
            #pragma unroll
            for (int q = 0; q < 2; q++)
                #pragma unroll
                for (int j = 0; j < 4; j++)
                    ra[q * 4 + j] = *(const float4*)&src[(size_t)(m0 + ar + q * 64) * K + k0g + ac + j * 16];
            #pragma unroll
            for (int j = 0; j < 8; j++)
                rb[j] = *(const float4*)&W[(size_t)(k0g + br) * 512 + n0 + bc + j * 16];
        }

        const uint32_t aHB = smem_to_u32(Ah);
        const uint32_t bHB = smem_to_u32(Bh);

        #pragma unroll
        for (int ks = 0; ks < 4; ks++) {
            const int k0 = ks * 16;
            uint32_t ah[2][4];
            #pragma unroll
            for (int mi = 0; mi < 2; mi++) {
                int row = wm * 32 + mi * 16 + (lane & 15);
                uint32_t off = (uint32_t)(row * 72 + k0 + (lane >> 4) * 8) * 2;
                ldsm_x4(ah[mi], aHB + off);
            }
            #pragma unroll
            for (int nc = 0; nc < 4; nc++) {
                int krow = k0 + (lane & 15);
                int ncol = wn * 64 + nc * 16 + (lane >> 4) * 8;
                uint32_t off = (uint32_t)(krow * 136 + ncol) * 2;
                uint32_t bh[4];
                ldsm_x4_t(bh, bHB + off);
                #pragma unroll
                for (int mi = 0; mi < 2; mi++) {
                    mma_f16(acc[mi][nc*2+0], ah[mi], bh);
                    mma_f16(acc[mi][nc*2+1], ah[mi], bh + 2);
                }
            }
        }
        __syncthreads();
    }

    // Epilogue: bias + tanh + store
    #pragma unroll
    for (int mi = 0; mi < 2; mi++) {
        #pragma unroll
        for (int ni = 0; ni < 8; ni++) {
            int m_g = m0 + wm * 32 + mi * 16 + (lane >> 2);
            int n_g = n0 + wn * 64 + ni * 8 + (lane & 3) * 2;
            float2 bv = *(const float2*)&bias[n_g];
            float2 o0, o1;
            o0.x = tanhf(acc[mi][ni][0] + bv.x);
            o0.y = tanhf(acc[mi][ni][1] + bv.y);
            o1.x = tanhf(acc[mi][ni][2] + bv.x);
            o1.y = tanhf(acc[mi][ni][3] + bv.y);
            *(float2*)&dst[(size_t)m_g * 512 + n_g] = o0;
            *(float2*)&dst[(size_t)(m_g + 8) * 512 + n_g] = o1;
        }
    }
}

// ---------------------------------------------------------------------------
// Dual attention: 4-t amortized smem reads + f32x2 + 8-way s-split.
// Block = (b, d-tile 32), 1024 threads: tid = sq*128 + tq*16 + dp
//   sq = s-chunk (0..7, 32 s each), tq = t-quad (0..7), dp = d-pair (0..15).
// Thread handles t = tq*4+ti (ti 0..3) x 2 d x 32 s: H/F/E read ONCE per s
// serves 8 exp evals -> smem crossbar traffic /4 vs R13.
// tanh-bounded logits -> no max subtraction. Partials merged via smem.
// Grid (16, 8) = 128 blocks, 132KB smem -> 1 block/SM, 32 warps/SM.
// ---------------------------------------------------------------------------
#define ATTN_SMEM ((24576 + 8192 + 1024) * 4)   // tiles + red2 + fin = 135168 B

__global__ void __launch_bounds__(1024)
attn_kernel(const float* __restrict__ H, const float* __restrict__ F,
            const float* __restrict__ Amat, const float* __restrict__ Cmat,
            const float* __restrict__ enc, const float* __restrict__ outp,
            float* __restrict__ concat, float* __restrict__ attn)
{
    extern __shared__ float sm[];
    float*  Hs   = sm;                       // [256][32]
    float*  Fs   = sm + 8192;                // [256][32]
    float*  Es   = sm + 16384;               // [256][32]
    float2* red2 = (float2*)(sm + 24576);    // [8 sq][32 t][16 dp]
    float2* fin  = (float2*)(sm + 32768);    // [32 t][16 dp]

    const int tid = threadIdx.x;
    const int dp  = tid & 15;
    const int tq  = (tid >> 4) & 7;
    const int sq  = tid >> 7;            // 0..7
    const int d0  = blockIdx.x * 32;
    const int b   = blockIdx.y;
    const int dl2 = dp * 2;

    // Load tiles (2048 float4 per tile, 1024 threads -> 2 iters)
    for (int idx = tid; idx < 2048; idx += 1024) {
        int s  = idx >> 3;
        int dl = (idx & 7) << 2;
        size_t g = ((size_t)(b * Ss + s)) * Dd + d0 + dl;
        *(float4*)&Hs[s * 32 + dl] = *(const float4*)&H[g];
        *(float4*)&Fs[s * 32 + dl] = *(const float4*)&F[g];
        *(float4*)&Es[s * 32 + dl] = *(const float4*)&enc[g];
    }
    __syncthreads();

    const float L2E = 1.4426950408889634f;
    ull a2[4], c2[4];
    #pragma unroll
    for (int ti = 0; ti < 4; ti++) {
        int m = b * Tt + tq * 4 + ti;
        float2 av = *(const float2*)&Amat[(size_t)m * Dd + d0 + dl2];
        float2 cv = *(const float2*)&Cmat[(size_t)m * Dd + d0 + dl2];
        a2[ti] = pack2(av.x * L2E, av.y * L2E);
        c2[ti] = pack2(cv.x * L2E, cv.y * L2E);
    }

    const int s0 = sq * 32;

    // Pass 1: partial softmax denominators (read H,F once per s -> 8 evals)
    float2 ps[4];
    #pragma unroll
    for (int ti = 0; ti < 4; ti++) ps[ti] = make_float2(0.f, 0.f);
    #pragma unroll 4
    for (int s = s0; s < s0 + 32; s++) {
        float2 hf = *(const float2*)&Hs[s * 32 + dl2];
        float2 ff = *(const float2*)&Fs[s * 32 + dl2];
        ull h2 = pack2(hf.x, hf.y);
        ull f2 = pack2(ff.x, ff.y);
        #pragma unroll
        for (int ti = 0; ti < 4; ti++) {
            ull l2 = fma2v(a2[ti], h2, mul2(c2[ti], f2));
            float lx, ly; unpack2(l2, lx, ly);
            ps[ti].x += exp2f(lx);
            ps[ti].y += exp2f(ly);
        }
    }
    #pragma unroll
    for (int ti = 0; ti < 4; ti++)
        red2[sq * 512 + (tq * 4 + ti) * 16 + dp] = ps[ti];
    __syncthreads();
    if (tid < 512) {
        float2 sacc = red2[tid];
        #pragma unroll
        for (int k = 1; k < 8; k++) {
            float2 r = red2[k * 512 + tid];
            sacc.x += r.x; sacc.y += r.y;
        }
        fin[tid] = make_float2(1.f / sacc.x, 1.f / sacc.y);
    }
    __syncthreads();
    ull inv2[4];
    #pragma unroll
    for (int ti = 0; ti < 4; ti++) {
        float2 iv = fin[(tq * 4 + ti) * 16 + dp];
        inv2[ti] = pack2(iv.x, iv.y);
    }

    // Pass 2: write gamma + partial context
    float2 pc[4];
    #pragma unroll
    for (int ti = 0; ti < 4; ti++) pc[ti] = make_float2(0.f, 0.f);
    #pragma unroll 2
    for (int s = s0; s < s0 + 32; s++) {
        float2 hf = *(const float2*)&Hs[s * 32 + dl2];
        float2 ff = *(const float2*)&Fs[s * 32 + dl2];
        float2 ef = *(const float2*)&Es[s * 32 + dl2];
        ull h2 = pack2(hf.x, hf.y);
        ull f2 = pack2(ff.x, ff.y);
        #pragma unroll
        for (int ti = 0; ti < 4; ti++) {
            ull l2 = fma2v(a2[ti], h2, mul2(c2[ti], f2));
            float lx, ly; unpack2(l2, lx, ly);
            ull g2 = mul2(pack2(exp2f(lx), exp2f(ly)), inv2[ti]);
            float gx, gy; unpack2(g2, gx, gy);
            int m = b * Tt + tq * 4 + ti;
            *(float2*)&attn[((size_t)m * Ss + s) * Dd + d0 + dl2] = make_float2(gx, gy);
            pc[ti].x = fmaf(gx, ef.x, pc[ti].x);
            pc[ti].y = fmaf(gy, ef.y, pc[ti].y);
        }
    }
    #pragma unroll
    for (int ti = 0; ti < 4; ti++)
        red2[sq * 512 + (tq * 4 + ti) * 16 + dp] = pc[ti];
    __syncthreads();
    if (tid < 512) {
        float2 cacc = red2[tid];
        #pragma unroll
        for (int k = 1; k < 8; k++) {
            float2 r = red2[k * 512 + tid];
            cacc.x += r.x; cacc.y += r.y;
        }
        int t  = tid >> 4;
        int dq = tid & 15;
        int m  = b * Tt + t;
        *(float2*)&concat[(size_t)m * (2 * Dd) + Dd + d0 + dq * 2] = cacc;
    } else {
        int idx = tid - 512;
        int t  = idx >> 4;
        int dq = idx & 15;
        int m  = b * Tt + t;
        *(float2*)&concat[(size_t)m * (2 * Dd) + d0 + dq * 2] =
            *(const float2*)&outp[(size_t)m * Dd + d0 + dq * 2];
    }
}

// ---------------------------------------------------------------------------
extern "C" void kernel_launch(void* const* d_in, const int* in_sizes, int n_in,
                              void* d_out, int out_size)
{
    const float* output = (const float*)d_in[0];   // [8,32,512]
    const float* enc    = (const float*)d_in[1];   // [256,8,512] flat [2048,512]
    const float* z      = (const float*)d_in[2];   // [8,256,128] flat [2048,128]
    const float* W1 = (const float*)d_in[3];
    const float* b1 = (const float*)d_in[4];
    const float* W2 = (const float*)d_in[5];
    const float* b2 = (const float*)d_in[6];
    const float* W3 = (const float*)d_in[7];
    const float* b3 = (const float*)d_in[8];
    const float* W4 = (const float*)d_in[9];
    const float* b4 = (const float*)d_in[10];

    float* concat = (float*)d_out;                       // [8,32,1024]
    float* attn   = concat + (size_t)Bb * Tt * 2 * Dd;   // [8,32,256,512]

    float *pH, *pF, *pA, *pC;
    cudaGetSymbolAddress((void**)&pH, g_H);
    cudaGetSymbolAddress((void**)&pF, g_F);
    cudaGetSymbolAddress((void**)&pA, g_A);
    cudaGetSymbolAddress((void**)&pC, g_C);

    cudaFuncSetAttribute(megagemm_mma, cudaFuncAttributeMaxDynamicSharedMemorySize, GEMM_SMEM);
    megagemm_mma<<<144, 256, GEMM_SMEM>>>(enc, z, output,
                                          W1, b1, W2, b2, W3, b3, W4, b4,
                                          pH, pF, pA, pC);

    cudaFuncSetAttribute(attn_kernel, cudaFuncAttributeMaxDynamicSharedMemorySize, ATTN_SMEM);
    attn_kernel<<<dim3(16, Bb), 1024, ATTN_SMEM>>>(pH, pF, pA, pC, enc, output, concat, attn);
}

// round 16
// speedup vs baseline: 1.1244x; 1.0048x over previous
#include <cuda_runtime.h>
#include <cuda_fp16.h>
#include <math.h>
#include <stdint.h>

#define Bb 8
#define Ss 256
#define Tt 32
#define Dd 512
#define NROWS 2048   // B*S
#define MROWS 256    // B*T

// Scratch (allocation-free rule: __device__ globals)
__device__ float g_H[NROWS * Dd];
__device__ float g_F[NROWS * Dd];
__device__ float g_A[MROWS * Dd];
__device__ float g_C[MROWS * Dd];

typedef unsigned long long ull;

// ---------------------------------------------------------------------------
// helpers
// ---------------------------------------------------------------------------
__device__ __forceinline__ uint32_t smem_to_u32(const void* p) {
    uint32_t a;
    asm("{ .reg .u64 t; cvta.to.shared.u64 t, %1; cvt.u32.u64 %0, t; }"
        : "=r"(a) : "l"(p));
    return a;
}
__device__ __forceinline__ void ldsm_x4(uint32_t* r, uint32_t addr) {
    asm volatile("ldmatrix.sync.aligned.m8n8.x4.shared.b16 {%0,%1,%2,%3}, [%4];"
        : "=r"(r[0]), "=r"(r[1]), "=r"(r[2]), "=r"(r[3]) : "r"(addr));
}
__device__ __forceinline__ void ldsm_x4_t(uint32_t* r, uint32_t addr) {
    asm volatile("ldmatrix.sync.aligned.m8n8.x4.trans.shared.b16 {%0,%1,%2,%3}, [%4];"
        : "=r"(r[0]), "=r"(r[1]), "=r"(r[2]), "=r"(r[3]) : "r"(addr));
}
__device__ __forceinline__ void mma_f16(float* d, const uint32_t* a, const uint32_t* b) {
    asm volatile("mma.sync.aligned.m16n8k16.row.col.f32.f16.f16.f32 "
        "{%0,%1,%2,%3}, {%4,%5,%6,%7}, {%8,%9}, {%0,%1,%2,%3};"
        : "+f"(d[0]), "+f"(d[1]), "+f"(d[2]), "+f"(d[3])
        : "r"(a[0]), "r"(a[1]), "r"(a[2]), "r"(a[3]), "r"(b[0]), "r"(b[1]));
}
__device__ __forceinline__ uint32_t pbh(__half a, __half b) {
    __half2 t; t.x = a; t.y = b;
    return *(uint32_t*)&t;
}
// packed f32x2
__device__ __forceinline__ ull pack2(float x, float y) {
    ull r;
    asm("mov.b64 %0, {%1, %2};" : "=l"(r) : "f"(x), "f"(y));
    return r;
}
__device__ __forceinline__ void unpack2(ull v, float& x, float& y) {
    asm("mov.b64 {%0, %1}, %2;" : "=f"(x), "=f"(y) : "l"(v));
}
__device__ __forceinline__ ull mul2(ull a, ull b) {
    ull d;
    asm("mul.rn.f32x2 %0, %1, %2;" : "=l"(d) : "l"(a), "l"(b));
    return d;
}
__device__ __forceinline__ ull fma2v(ull a, ull b, ull c) {
    ull d;
    asm("fma.rn.f32x2 %0, %1, %2, %3;" : "=l"(d) : "l"(a), "l"(b), "l"(c));
    return d;
}

// ---------------------------------------------------------------------------
// Mega-GEMM: out = tanh(src @ W + bias), pure fp16 operands, fp32 accum.
// CTA: 128m x 64n, BK=64 -> 288 CTAs, 55.3KB smem + <=128 regs -> ALL CTAs
// co-resident (2/SM, single wave): staging of one CTA hides under the
// other's MMA burst. W traffic doubles (L2-resident, free); A unchanged.
// smem/buffer (halfs): Ah[128*72]=9216, Bh[64*72]=4608 -> 13824.
// Blocks: [0,128) H (K=512) | [128,144) A | [144,160) C | [160,288) F (K=128)
// ---------------------------------------------------------------------------
#define A_ELE (128 * 72)
#define B_ELE (64 * 72)
#define BUF_ELE (A_ELE + B_ELE)              // 13824 halfs
#define GEMM_SMEM (2 * BUF_ELE * 2)          // 55296 bytes

__global__ void __launch_bounds__(256, 2)
megagemm_mma(const float* __restrict__ enc, const float* __restrict__ z,
             const float* __restrict__ outp,
             const float* __restrict__ W1, const float* __restrict__ b1,
             const float* __restrict__ W2, const float* __restrict__ b2,
             const float* __restrict__ W3, const float* __restrict__ b3,
             const float* __restrict__ W4, const float* __restrict__ b4,
             float* __restrict__ H, float* __restrict__ F,
             float* __restrict__ A, float* __restrict__ C)
{
    extern __shared__ __half sbuf[];

    int bid = blockIdx.x;
    const float *src, *W, *bias;
    float* dst;
    int K;
    if (bid < 128)      { src = enc;  W = W1; bias = b1; dst = H; K = 512; }
    else if (bid < 144) { src = outp; W = W2; bias = b2; dst = A; K = 512; bid -= 128; }
    else if (bid < 160) { src = outp; W = W4; bias = b4; dst = C; K = 512; bid -= 144; }
    else                { src = z;    W = W3; bias = b3; dst = F; K = 128; bid -= 160; }
    const int nb = bid & 7;          // 512/64 = 8 n-blocks
    const int mb = bid >> 3;
    const int m0 = mb * 128, n0 = nb * 64;

    const int tid  = threadIdx.x;
    const int lane = tid & 31;
    const int wid  = tid >> 5;
    const int wm   = wid & 3;     // 32 m rows
    const int wn   = wid >> 2;    // 32 n cols

    // staging coordinates
    const int ar = tid >> 2;             // A row base (0..63, +64)
    const int ac = (tid & 3) * 4;        // A col base (+j*16)
    const int br = tid >> 2;             // B k-row (0..63)
    const int bc = (tid & 3) * 4;        // B col base (+j*16)

    float acc[2][4][4];
    #pragma unroll
    for (int i = 0; i < 2; i++)
        #pragma unroll
        for (int j = 0; j < 4; j++)
            #pragma unroll
            for (int q = 0; q < 4; q++) acc[i][j][q] = 0.f;

    const int nch = K >> 6;
    float4 ra[8], rb[4];

    // Prologue: load chunk 0
    #pragma unroll
    for (int q = 0; q < 2; q++)
        #pragma unroll
        for (int j = 0; j < 4; j++)
            ra[q * 4 + j] = *(const float4*)&src[(size_t)(m0 + ar + q * 64) * K + ac + j * 16];
    #pragma unroll
    for (int j = 0; j < 4; j++)
        rb[j] = *(const float4*)&W[(size_t)br * 512 + n0 + bc + j * 16];

    for (int c = 0; c < nch; c++) {
        const int buf = c & 1;
        __half* Ah = sbuf + buf * BUF_ELE;
        __half* Bh = Ah + A_ELE;

        // Convert prefetched registers -> smem (single fp16 plane)
        #pragma unroll
        for (int q = 0; q < 2; q++)
            #pragma unroll
            for (int j = 0; j < 4; j++) {
                float4 v = ra[q * 4 + j];
                uint2 uh;
                uh.x = pbh(__float2half_rn(v.x), __float2half_rn(v.y));
                uh.y = pbh(__float2half_rn(v.z), __float2half_rn(v.w));
                *(uint2*)&Ah[(ar + q * 64) * 72 + ac + j * 16] = uh;
            }
        #pragma unroll
        for (int j = 0; j < 4; j++) {
            float4 v = rb[j];
            uint2 uh;
            uh.x = pbh(__float2half_rn(v.x), __float2half_rn(v.y));
            uh.y = pbh(__float2half_rn(v.z), __float2half_rn(v.w));
            *(uint2*)&Bh[br * 72 + bc + j * 16] = uh;
        }
        __syncthreads();

        // Prefetch next chunk while MMAs run
        if (c + 1 < nch) {
            const int k0g = (c + 1) * 64;
            #pragma unroll
            for (int q = 0; q < 2; q++)
                #pragma unroll
                for (int j = 0; j < 4; j++)
                    ra[q * 4 + j] = *(const float4*)&src[(size_t)(m0 + ar + q * 64) * K + k0g + ac + j * 16];
            #pragma unroll
            for (int j = 0; j < 4; j++)
                rb[j] = *(const float4*)&W[(size_t)(k0g + br) * 512 + n0 + bc + j * 16];
        }

        const uint32_t aHB = smem_to_u32(Ah);
        const uint32_t bHB = smem_to_u32(Bh);

        #pragma unroll
        for (int ks = 0; ks < 4; ks++) {
            const int k0 = ks * 16;
            uint32_t ah[2][4];
            #pragma unroll
            for (int mi = 0; mi < 2; mi++) {
                int row = wm * 32 + mi * 16 + (lane & 15);
                uint32_t off = (uint32_t)(row * 72 + k0 + (lane >> 4) * 8) * 2;
                ldsm_x4(ah[mi], aHB + off);
            }
            #pragma unroll
            for (int nc = 0; nc < 2; nc++) {
                int krow = k0 + (lane & 15);
                int ncol = wn * 32 + nc * 16 + (lane >> 4) * 8;
                uint32_t off = (uint32_t)(krow * 72 + ncol) * 2;
                uint32_t bh[4];
                ldsm_x4_t(bh, bHB + off);
                #pragma unroll
                for (int mi = 0; mi < 2; mi++) {
                    mma_f16(acc[mi][nc*2+0], ah[mi], bh);
                    mma_f16(acc[mi][nc*2+1], ah[mi], bh + 2);
                }
            }
        }
        __syncthreads();
    }

    // Epilogue: bias + tanh + store
    #pragma unroll
    for (int mi = 0; mi < 2; mi++) {
        #pragma unroll
        for (int ni = 0; ni < 4; ni++) {
            int m_g = m0 + wm * 32 + mi * 16 + (lane >> 2);
            int n_g = n0 + wn * 32 + ni * 8 + (lane & 3) * 2;
            float2 bv = *(const float2*)&bias[n_g];
            float2 o0, o1;
            o0.x = tanhf(acc[mi][ni][0] + bv.x);
            o0.y = tanhf(acc[mi][ni][1] + bv.y);
            o1.x = tanhf(acc[mi][ni][2] + bv.x);
            o1.y = tanhf(acc[mi][ni][3] + bv.y);
            *(float2*)&dst[(size_t)m_g * 512 + n_g] = o0;
            *(float2*)&dst[(size_t)(m_g + 8) * 512 + n_g] = o1;
        }
    }
}

// ---------------------------------------------------------------------------
// Dual attention: 4-t amortized smem reads + f32x2 + 8-way s-split
// (R15 proven: 33.8us; register-file-capped at 1024 thr/SM -> keep as-is).
// Block = (b, d-tile 32), 1024 threads: tid = sq*128 + tq*16 + dp.
// tanh-bounded logits -> no max subtraction. Partials merged via smem.
// Grid (16, 8) = 128 blocks.
// ---------------------------------------------------------------------------
#define ATTN_SMEM ((24576 + 8192 + 1024) * 4)   // tiles + red2 + fin = 135168 B

__global__ void __launch_bounds__(1024)
attn_kernel(const float* __restrict__ H, const float* __restrict__ F,
            const float* __restrict__ Amat, const float* __restrict__ Cmat,
            const float* __restrict__ enc, const float* __restrict__ outp,
            float* __restrict__ concat, float* __restrict__ attn)
{
    extern __shared__ float sm[];
    float*  Hs   = sm;                       // [256][32]
    float*  Fs   = sm + 8192;                // [256][32]
    float*  Es   = sm + 16384;               // [256][32]
    float2* red2 = (float2*)(sm + 24576);    // [8 sq][32 t][16 dp]
    float2* fin  = (float2*)(sm + 32768);    // [32 t][16 dp]

    const int tid = threadIdx.x;
    const int dp  = tid & 15;
    const int tq  = (tid >> 4) & 7;
    const int sq  = tid >> 7;            // 0..7
    const int d0  = blockIdx.x * 32;
    const int b   = blockIdx.y;
    const int dl2 = dp * 2;

    for (int idx = tid; idx < 2048; idx += 1024) {
        int s  = idx >> 3;
        int dl = (idx & 7) << 2;
        size_t g = ((size_t)(b * Ss + s)) * Dd + d0 + dl;
        *(float4*)&Hs[s * 32 + dl] = *(const float4*)&H[g];
        *(float4*)&Fs[s * 32 + dl] = *(const float4*)&F[g];
        *(float4*)&Es[s * 32 + dl] = *(const float4*)&enc[g];
    }
    __syncthreads();

    const float L2E = 1.4426950408889634f;
    ull a2[4], c2[4];
    #pragma unroll
    for (int ti = 0; ti < 4; ti++) {
        int m = b * Tt + tq * 4 + ti;
        float2 av = *(const float2*)&Amat[(size_t)m * Dd + d0 + dl2];
        float2 cv = *(const float2*)&Cmat[(size_t)m * Dd + d0 + dl2];
        a2[ti] = pack2(av.x * L2E, av.y * L2E);
        c2[ti] = pack2(cv.x * L2E, cv.y * L2E);
    }

    const int s0 = sq * 32;

    float2 ps[4];
    #pragma unroll
    for (int ti = 0; ti < 4; ti++) ps[ti] = make_float2(0.f, 0.f);
    #pragma unroll 4
    for (int s = s0; s < s0 + 32; s++) {
        float2 hf = *(const float2*)&Hs[s * 32 + dl2];
        float2 ff = *(const float2*)&Fs[s * 32 + dl2];
        ull h2 = pack2(hf.x, hf.y);
        ull f2 = pack2(ff.x, ff.y);
        #pragma unroll
        for (int ti = 0; ti < 4; ti++) {
            ull l2 = fma2v(a2[ti], h2, mul2(c2[ti], f2));
            float lx, ly; unpack2(l2, lx, ly);
            ps[ti].x += exp2f(lx);
            ps[ti].y += exp2f(ly);
        }
    }
    #pragma unroll
    for (int ti = 0; ti < 4; ti++)
        red2[sq * 512 + (tq * 4 + ti) * 16 + dp] = ps[ti];
    __syncthreads();
    if (tid < 512) {
        float2 sacc = red2[tid];
        #pragma unroll
        for (int k = 1; k < 8; k++) {
            float2 r = red2[k * 512 + tid];
            sacc.x += r.x; sacc.y += r.y;
        }
        fin[tid] = make_float2(1.f / sacc.x, 1.f / sacc.y);
    }
    __syncthreads();
    ull inv2[4];
    #pragma unroll
    for (int ti = 0; ti < 4; ti++) {
        float2 iv = fin[(tq * 4 + ti) * 16 + dp];
        inv2[ti] = pack2(iv.x, iv.y);
    }

    float2 pc[4];
    #pragma unroll
    for (int ti = 0; ti < 4; ti++) pc[ti] = make_float2(0.f, 0.f);
    #pragma unroll 2
    for (int s = s0; s < s0 + 32; s++) {
        float2 hf = *(const float2*)&Hs[s * 32 + dl2];
        float2 ff = *(const float2*)&Fs[s * 32 + dl2];
        float2 ef = *(const float2*)&Es[s * 32 + dl2];
        ull h2 = pack2(hf.x, hf.y);
        ull f2 = pack2(ff.x, ff.y);
        #pragma unroll
        for (int ti = 0; ti < 4; ti++) {
            ull l2 = fma2v(a2[ti], h2, mul2(c2[ti], f2));
            float lx, ly; unpack2(l2, lx, ly);
            ull g2 = mul2(pack2(exp2f(lx), exp2f(ly)), inv2[ti]);
            float gx, gy; unpack2(g2, gx, gy);
            int m = b * Tt + tq * 4 + ti;
            *(float2*)&attn[((size_t)m * Ss + s) * Dd + d0 + dl2] = make_float2(gx, gy);
            pc[ti].x = fmaf(gx, ef.x, pc[ti].x);
            pc[ti].y = fmaf(gy, ef.y, pc[ti].y);
        }
    }
    #pragma unroll
    for (int ti = 0; ti < 4; ti++)
        red2[sq * 512 + (tq * 4 + ti) * 16 + dp] = pc[ti];
    __syncthreads();
    if (tid < 512) {
        float2 cacc = red2[tid];
        #pragma unroll
        for (int k = 1; k < 8; k++) {
            float2 r = red2[k * 512 + tid];
            cacc.x += r.x; cacc.y += r.y;
        }
        int t  = tid >> 4;
        int dq = tid & 15;
        int m  = b * Tt + t;
        *(float2*)&concat[(size_t)m * (2 * Dd) + Dd + d0 + dq * 2] = cacc;
    } else {
        int idx = tid - 512;
        int t  = idx >> 4;
        int dq = idx & 15;
        int m  = b * Tt + t;
        *(float2*)&concat[(size_t)m * (2 * Dd) + d0 + dq * 2] =
            *(const float2*)&outp[(size_t)m * Dd + d0 + dq * 2];
    }
}

// ---------------------------------------------------------------------------
extern "C" void kernel_launch(void* const* d_in, const int* in_sizes, int n_in,
                              void* d_out, int out_size)
{
    const float* output = (const float*)d_in[0];   // [8,32,512]
    const float* enc    = (const float*)d_in[1];   // [256,8,512] flat [2048,512]
    const float* z      = (const float*)d_in[2];   // [8,256,128] flat [2048,128]
    const float* W1 = (const float*)d_in[3];
    const float* b1 = (const float*)d_in[4];
    const float* W2 = (const float*)d_in[5];
    const float* b2 = (const float*)d_in[6];
    const float* W3 = (const float*)d_in[7];
    const float* b3 = (const float*)d_in[8];
    const float* W4 = (const float*)d_in[9];
    const float* b4 = (const float*)d_in[10];

    float* concat = (float*)d_out;                       // [8,32,1024]
    float* attn   = concat + (size_t)Bb * Tt * 2 * Dd;   // [8,32,256,512]

    float *pH, *pF, *pA, *pC;
    cudaGetSymbolAddress((void**)&pH, g_H);
    cudaGetSymbolAddress((void**)&pF, g_F);
    cudaGetSymbolAddress((void**)&pA, g_A);
    cudaGetSymbolAddress((void**)&pC, g_C);

    cudaFuncSetAttribute(megagemm_mma, cudaFuncAttributeMaxDynamicSharedMemorySize, GEMM_SMEM);
    megagemm_mma<<<288, 256, GEMM_SMEM>>>(enc, z, output,
                                          W1, b1, W2, b2, W3, b3, W4, b4,
                                          pH, pF, pA, pC);

    cudaFuncSetAttribute(attn_kernel, cudaFuncAttributeMaxDynamicSharedMemorySize, ATTN_SMEM);
    attn_kernel<<<dim3(16, Bb), 1024, ATTN_SMEM>>>(pH, pF, pA, pC, enc, output, concat, attn);
}